// round 4
// baseline (speedup 1.0000x reference)
#include <cuda_runtime.h>

#define T_LEN  1024
#define NSTEP  1023
#define B_SZ   8192

typedef unsigned long long ull;

// scratch: time-major inputs + c_t buffer
__device__ int   g_act_t[T_LEN * B_SZ];            // [t][b]
__device__ float g_rew_t[T_LEN * B_SZ];            // [t][b]
__device__ float g_c[(size_t)B_SZ * NSTEP * 4];    // [b][t][4]

// ---------------- packed f32x2 helpers ----------------
__device__ __forceinline__ void ffma2(ull& d, ull a, ull b) {
    asm("fma.rn.f32x2 %0, %1, %2, %0;" : "+l"(d) : "l"(a), "l"(b));
}
__device__ __forceinline__ ull mul2(ull a, ull b) {
    ull r; asm("mul.rn.f32x2 %0, %1, %2;" : "=l"(r) : "l"(a), "l"(b)); return r;
}
__device__ __forceinline__ ull add2(ull a, ull b) {
    ull r; asm("add.rn.f32x2 %0, %1, %2;" : "=l"(r) : "l"(a), "l"(b)); return r;
}
__device__ __forceinline__ ull pack2(float x, float y) {
    ull r; asm("mov.b64 %0, {%1, %2};" : "=l"(r) : "f"(x), "f"(y)); return r;
}
__device__ __forceinline__ float2 unpack2(ull v) {
    float2 r; asm("mov.b64 {%0, %1}, %2;" : "=f"(r.x), "=f"(r.y) : "l"(v)); return r;
}
__device__ __forceinline__ ull shflx64(ull v, int m) {
    return __shfl_xor_sync(0xFFFFFFFFu, v, m);
}
__device__ __forceinline__ float tanh_fast(float x) {   // ~1e-6 abs err
    float e, r;
    asm("ex2.approx.f32 %0, %1;" : "=f"(e) : "f"(x * 2.8853900817779268f));
    asm("rcp.approx.f32 %0, %1;" : "=f"(r) : "f"(e + 1.0f));
    return fmaf(-2.0f, r, 1.0f);
}

// ---------------- transpose [B][T] -> [T][B] ----------------
__global__ void __launch_bounds__(256)
transpose_kernel(const int* __restrict__ act, const float* __restrict__ rew) {
    __shared__ unsigned tile[32][33];
    const int tt = blockIdx.x * 32, tb = blockIdx.y * 32;
    const unsigned* src = (blockIdx.z == 0) ? (const unsigned*)act : (const unsigned*)rew;
    unsigned*       dst = (blockIdx.z == 0) ? (unsigned*)g_act_t  : (unsigned*)g_rew_t;
    const int tx = threadIdx.x, ty = threadIdx.y;
    #pragma unroll
    for (int i = 0; i < 32; i += 8)
        tile[ty + i][tx] = src[(long long)(tb + ty + i) * T_LEN + tt + tx];
    __syncthreads();
    #pragma unroll
    for (int i = 0; i < 32; i += 8)
        dst[(long long)(tt + ty + i) * B_SZ + tb + tx] = tile[tx][ty + i];
}

// ---------------- main recurrent kernel ----------------
// grid = 1024 CTAs x 64 thr. CTA c covers batch elements [8c, 8c+8).
//   warp 0 = reward module, warp 1 = action-history module (independent, no barriers).
// Within a warp, 4 lanes per element: lane ll owns rows [8ll,8ll+8) and state
// dims [8ll,8ll+8) (4 f32x2 regs). Full 32-dim state is rebuilt each step via a
// 2-round xor butterfly into LANE-RELATIVE segment order [ll, ll^1, ll^2, ll^3];
// weights are pre-permuted per-ll in SMEM to match that order.
__global__ void __launch_bounds__(64, 7)
memann_mod(const float* __restrict__ w_r1, const float* __restrict__ b_r1,
           const float* __restrict__ w_r2, const float* __restrict__ b_r2,
           const float* __restrict__ w_a1, const float* __restrict__ b_a1,
           const float* __restrict__ w_a2, const float* __restrict__ b_a2,
           float*       __restrict__ out)
{
    // ll-stride 130 ull = 1040B -> the 4 lane addresses land in distinct 32B
    // quads of the 128B crossbar line: conflict-free LDS.128 broadcasts.
    __shared__ __align__(16) ull wrs[4][130];      // [ll][r*16 + p]
    __shared__ __align__(16) ull was[4][130];
    __shared__ __align__(16) ull colba[4][4][4];   // [a][ll][rp] = {w_a1[row][a]+b_a1, row+1}

    const int tid = threadIdx.x;

    // ---- one-time staging (pre-permuted per ll) ----
    for (int i = tid; i < 512; i += 64) {
        const int ll = i >> 7, r = (i >> 4) & 7, p = i & 15;
        const int seg = p >> 2, u = p & 3;
        const int gcol = 8 * (ll ^ seg) + 2 * u;
        const int row  = 8 * ll + r;
        wrs[ll][r * 16 + p] = pack2(w_r1[row * 33 + 1 + gcol], w_r1[row * 33 + 2 + gcol]);
        was[ll][r * 16 + p] = pack2(w_a1[row * 36 + 4 + gcol], w_a1[row * 36 + 5 + gcol]);
    }
    {
        const int a = tid >> 4, ll = (tid >> 2) & 3, rp = tid & 3;
        const int row = 8 * ll + 2 * rp;
        colba[a][ll][rp] = pack2(w_a1[row * 36 + a] + b_a1[row],
                                 w_a1[(row + 1) * 36 + a] + b_a1[row + 1]);
    }
    __syncthreads();

    const int lane = tid & 31;
    const int wid  = tid >> 5;           // 0 = reward, 1 = action
    const int eg   = lane >> 2;          // element within warp (0..7)
    const int ll   = lane & 3;           // sub-lane: rows/dims [8ll, 8ll+8)
    const long long b = (long long)blockIdx.x * 8 + eg;
    const int*   ap  = g_act_t + b;
    const float* rp_ = g_rew_t + b;

    ull fullv[16];
    #pragma unroll
    for (int p = 0; p < 16; p++) fullv[p] = 0ull;

    if (wid == 0) {
        // ---------------- reward module ----------------
        ull bw[8], w2s[4];
        #pragma unroll
        for (int r = 0; r < 8; r++) {
            const int row = 8 * ll + r;
            bw[r] = pack2(b_r1[row], w_r1[row * 33]);    // {bias, w_r1[:,0]}
        }
        #pragma unroll
        for (int u = 0; u < 4; u++)
            w2s[u] = pack2(w_r2[8 * ll + 2 * u], w_r2[8 * ll + 2 * u + 1]);
        const float br2 = b_r2[0];
        float q = 0.0f;
        float* op = out + ((size_t)b * NSTEP) * 4 + ll;

        int   a_cur = ap[0];
        float r_cur = rp_[0];
        for (int t = 0; t < NSTEP; t++) {
            const int   a_nxt = ap[(t + 1) * B_SZ];
            const float r_nxt = rp_[(t + 1) * B_SZ];

            const ull rv2 = pack2(1.0f, r_cur);
            ull acc[8];
            #pragma unroll
            for (int r = 0; r < 8; r++) acc[r] = mul2(bw[r], rv2);  // {b, wc0*r}
            #pragma unroll
            for (int pp = 0; pp < 8; pp++) {
                #pragma unroll
                for (int r = 0; r < 8; r++) {
                    const ulonglong2 w = *(const ulonglong2*)&wrs[ll][r * 16 + 2 * pp];
                    ffma2(acc[r], w.x, fullv[2 * pp]);
                    ffma2(acc[r], w.y, fullv[2 * pp + 1]);
                }
            }
            float sn[8];
            #pragma unroll
            for (int r = 0; r < 8; r++) {
                const float2 u = unpack2(acc[r]);
                sn[r] = tanh_fast(u.x + u.y);
            }
            ull s[4];
            #pragma unroll
            for (int u = 0; u < 4; u++) s[u] = pack2(sn[2 * u], sn[2 * u + 1]);

            // q_new = w_r2 . sr_t + b_r2 : own-segment partial + 4-lane reduce
            ull qa = 0ull;
            #pragma unroll
            for (int u = 0; u < 4; u++) ffma2(qa, w2s[u], s[u]);
            const float2 qf = unpack2(qa);
            float qs = qf.x + qf.y;
            qs += __shfl_xor_sync(0xFFFFFFFFu, qs, 1);
            qs += __shfl_xor_sync(0xFFFFFFFFu, qs, 2);
            const float q_new = qs + br2;

            q = (a_cur == ll) ? q_new : q * 0.95f;
            op[(size_t)t * 4] = q;

            // butterfly gather of new state into lane-relative order
            #pragma unroll
            for (int u = 0; u < 4; u++) fullv[u] = s[u];
            #pragma unroll
            for (int u = 0; u < 4; u++) fullv[4 + u] = shflx64(s[u], 1);
            #pragma unroll
            for (int u = 0; u < 8; u++) fullv[8 + u] = shflx64(fullv[u], 2);

            a_cur = a_nxt; r_cur = r_nxt;
        }
    } else {
        // ---------------- action-history module ----------------
        ull w2a[4][4];
        #pragma unroll
        for (int k = 0; k < 4; k++)
            #pragma unroll
            for (int u = 0; u < 4; u++)
                w2a[k][u] = pack2(w_a2[k * 32 + 8 * ll + 2 * u],
                                  w_a2[k * 32 + 8 * ll + 2 * u + 1]);
        const float ba = b_a2[ll];
        float* cp = g_c + ((size_t)b * NSTEP) * 4 + ll;

        int a_cur = ap[0];
        for (int t = 0; t < NSTEP; t++) {
            const int a_nxt = ap[(t + 1) * B_SZ];

            ull acc[8];
            #pragma unroll
            for (int r = 0; r < 8; r++) acc[r] = 0ull;
            #pragma unroll
            for (int pp = 0; pp < 8; pp++) {
                #pragma unroll
                for (int r = 0; r < 8; r++) {
                    const ulonglong2 w = *(const ulonglong2*)&was[ll][r * 16 + 2 * pp];
                    ffma2(acc[r], w.x, fullv[2 * pp]);
                    ffma2(acc[r], w.y, fullv[2 * pp + 1]);
                }
            }
            // one-hot column + bias (per a_cur), rows owned by this lane
            const ulonglong2 cbA = *(const ulonglong2*)&colba[a_cur][ll][0];
            const ulonglong2 cbB = *(const ulonglong2*)&colba[a_cur][ll][2];
            const float2 c0f = unpack2(cbA.x), c1f = unpack2(cbA.y);
            const float2 c2f = unpack2(cbB.x), c3f = unpack2(cbB.y);
            const float cbv[8] = {c0f.x, c0f.y, c1f.x, c1f.y, c2f.x, c2f.y, c3f.x, c3f.y};

            float sn[8];
            #pragma unroll
            for (int r = 0; r < 8; r++) {
                const float2 u = unpack2(acc[r]);
                sn[r] = tanh_fast(u.x + u.y + cbv[r]);
            }
            ull s[4];
            #pragma unroll
            for (int u = 0; u < 4; u++) s[u] = pack2(sn[2 * u], sn[2 * u + 1]);

            // c_k partials over own 8 dims, then packed 4-lane reduce
            ull ca0 = 0ull, ca1 = 0ull, ca2 = 0ull, ca3 = 0ull;
            #pragma unroll
            for (int u = 0; u < 4; u++) {
                ffma2(ca0, w2a[0][u], s[u]);
                ffma2(ca1, w2a[1][u], s[u]);
                ffma2(ca2, w2a[2][u], s[u]);
                ffma2(ca3, w2a[3][u], s[u]);
            }
            const float2 f0 = unpack2(ca0), f1 = unpack2(ca1);
            const float2 f2 = unpack2(ca2), f3 = unpack2(ca3);
            ull v01 = pack2(f0.x + f0.y, f1.x + f1.y);
            ull v23 = pack2(f2.x + f2.y, f3.x + f3.y);
            v01 = add2(v01, shflx64(v01, 1));
            v23 = add2(v23, shflx64(v23, 1));
            v01 = add2(v01, shflx64(v01, 2));
            v23 = add2(v23, shflx64(v23, 2));
            const ull    vsel = (ll & 2) ? v23 : v01;
            const float2 vv   = unpack2(vsel);
            const float  cval = ((ll & 1) ? vv.y : vv.x) + ba;
            cp[(size_t)t * 4] = cval;

            // butterfly gather of new state
            #pragma unroll
            for (int u = 0; u < 4; u++) fullv[u] = s[u];
            #pragma unroll
            for (int u = 0; u < 4; u++) fullv[4 + u] = shflx64(s[u], 1);
            #pragma unroll
            for (int u = 0; u < 8; u++) fullv[8 + u] = shflx64(fullv[u], 2);

            a_cur = a_nxt;
        }
    }
}

// ---------------- out += c ----------------
__global__ void __launch_bounds__(256)
add_kernel(float* __restrict__ out) {
    const size_t n4 = (size_t)B_SZ * NSTEP;        // float4 count
    float4* o = (float4*)out;
    const float4* c = (const float4*)g_c;
    for (size_t i = (size_t)blockIdx.x * 256 + threadIdx.x; i < n4;
         i += (size_t)gridDim.x * 256) {
        float4 a = o[i], b = c[i];
        a.x += b.x; a.y += b.y; a.z += b.z; a.w += b.w;
        o[i] = a;
    }
}

extern "C" void kernel_launch(void* const* d_in, const int* in_sizes, int n_in,
                              void* d_out, int out_size) {
    (void)in_sizes; (void)n_in; (void)out_size;
    transpose_kernel<<<dim3(T_LEN / 32, B_SZ / 32, 2), dim3(32, 8)>>>(
        (const int*)d_in[0], (const float*)d_in[1]);
    memann_mod<<<1024, 64>>>(
        (const float*)d_in[2], (const float*)d_in[3],
        (const float*)d_in[4], (const float*)d_in[5],
        (const float*)d_in[6], (const float*)d_in[7],
        (const float*)d_in[8], (const float*)d_in[9],
        (float*)d_out);
    add_kernel<<<2048, 256>>>((float*)d_out);
}

// round 5
// speedup vs baseline: 1.0559x; 1.0559x over previous
#include <cuda_runtime.h>

#define T_LEN  1024
#define NSTEP  1023
#define B_SZ   8192

typedef unsigned long long ull;

// scratch: time-major inputs + c_t buffer
__device__ int   g_act_t[T_LEN * B_SZ];            // [t][b]
__device__ float g_rew_t[T_LEN * B_SZ];            // [t][b]
__device__ float g_c[(size_t)B_SZ * NSTEP * 4];    // [b][t][4]

// ---------------- packed f32x2 helpers ----------------
__device__ __forceinline__ void ffma2(ull& d, ull a, ull b) {
    asm("fma.rn.f32x2 %0, %1, %2, %0;" : "+l"(d) : "l"(a), "l"(b));
}
__device__ __forceinline__ ull mul2(ull a, ull b) {
    ull r; asm("mul.rn.f32x2 %0, %1, %2;" : "=l"(r) : "l"(a), "l"(b)); return r;
}
__device__ __forceinline__ ull add2(ull a, ull b) {
    ull r; asm("add.rn.f32x2 %0, %1, %2;" : "=l"(r) : "l"(a), "l"(b)); return r;
}
__device__ __forceinline__ ull pack2(float x, float y) {
    ull r; asm("mov.b64 %0, {%1, %2};" : "=l"(r) : "f"(x), "f"(y)); return r;
}
__device__ __forceinline__ float2 unpack2(ull v) {
    float2 r; asm("mov.b64 {%0, %1}, %2;" : "=f"(r.x), "=f"(r.y) : "l"(v)); return r;
}
__device__ __forceinline__ ull shflx64(ull v, int m) {
    return __shfl_xor_sync(0xFFFFFFFFu, v, m);
}
// input already pre-scaled by 2*log2(e):  tanh = 1 - 2/(2^x' + 1)
__device__ __forceinline__ float tanh_pre(float xs) {
    float e, r;
    asm("ex2.approx.f32 %0, %1;" : "=f"(e) : "f"(xs));
    asm("rcp.approx.f32 %0, %1;" : "=f"(r) : "f"(e + 1.0f));
    return fmaf(-2.0f, r, 1.0f);
}

#define TANH_SC 2.8853900817779268f   // 2*log2(e)

// ---------------- transpose [B][T] -> [T][B] ----------------
__global__ void __launch_bounds__(256)
transpose_kernel(const int* __restrict__ act, const float* __restrict__ rew) {
    __shared__ unsigned tile[32][33];
    const int tt = blockIdx.x * 32, tb = blockIdx.y * 32;
    const unsigned* src = (blockIdx.z == 0) ? (const unsigned*)act : (const unsigned*)rew;
    unsigned*       dst = (blockIdx.z == 0) ? (unsigned*)g_act_t  : (unsigned*)g_rew_t;
    const int tx = threadIdx.x, ty = threadIdx.y;
    #pragma unroll
    for (int i = 0; i < 32; i += 8)
        tile[ty + i][tx] = src[(long long)(tb + ty + i) * T_LEN + tt + tx];
    __syncthreads();
    #pragma unroll
    for (int i = 0; i < 32; i += 8)
        dst[(long long)(tt + ty + i) * B_SZ + tb + tx] = tile[tx][ty + i];
}

// ---------------- main recurrent kernel ----------------
// grid = 1024 CTAs x 64 thr (2 warps). CTA < 512: reward module; >= 512: action.
// Each warp owns 8 elements; 4 lanes/element (lane ll handles rows/dims
// [8ll,8ll+8)). State is kept in double-buffered SMEM per element (natural
// order); each step: matvec streams state via LDS.128, lane writes its new
// 8 dims via 2 STS.128, one __syncwarp. No register butterfly, no reg caps.
__global__ void __launch_bounds__(64)
memann_mod(const float* __restrict__ w_r1, const float* __restrict__ b_r1,
           const float* __restrict__ w_r2, const float* __restrict__ b_r2,
           const float* __restrict__ w_a1, const float* __restrict__ b_a1,
           const float* __restrict__ w_a2, const float* __restrict__ b_a2,
           float*       __restrict__ out)
{
    // weights: [ll][r*16 + p]  (row = 8ll + r, p = x-pair index) — pre-scaled
    __shared__ __align__(16) ull w1s[4][130];
    // action one-hot column + bias (pre-scaled): [a][ll][rp] = {row, row+1}
    __shared__ __align__(16) ull colba[4][4][4];
    // state, double buffered: [wid][parity][element][pair]; stride 18 -> banks 4e
    __shared__ __align__(16) ull st[2][2][8][18];

    const int tid = threadIdx.x;
    const bool is_rew = blockIdx.x < 512;

    // ---- one-time staging ----
    if (is_rew) {
        for (int i = tid; i < 512; i += 64) {
            const int ll = i >> 7, r = (i >> 4) & 7, p = i & 15;
            const int row = 8 * ll + r;
            w1s[ll][r * 16 + p] = pack2(w_r1[row * 33 + 1 + 2 * p] * TANH_SC,
                                        w_r1[row * 33 + 2 + 2 * p] * TANH_SC);
        }
    } else {
        for (int i = tid; i < 512; i += 64) {
            const int ll = i >> 7, r = (i >> 4) & 7, p = i & 15;
            const int row = 8 * ll + r;
            w1s[ll][r * 16 + p] = pack2(w_a1[row * 36 + 4 + 2 * p] * TANH_SC,
                                        w_a1[row * 36 + 5 + 2 * p] * TANH_SC);
        }
        {
            const int a = tid >> 4, ll = (tid >> 2) & 3, rp = tid & 3;
            const int row = 8 * ll + 2 * rp;
            colba[a][ll][rp] =
                pack2((w_a1[row * 36 + a] + b_a1[row]) * TANH_SC,
                      (w_a1[(row + 1) * 36 + a] + b_a1[row + 1]) * TANH_SC);
        }
    }
    for (int i = tid; i < 2 * 2 * 8 * 18; i += 64) (&st[0][0][0][0])[i] = 0ull;
    __syncthreads();

    const int lane = tid & 31, wid = tid >> 5;
    const int e  = lane >> 2;          // element within warp
    const int ll = lane & 3;           // sub-lane: rows/dims [8ll, 8ll+8)
    const long long b =
        (long long)(is_rew ? blockIdx.x : blockIdx.x - 512) * 16 + wid * 8 + e;
    const int*   ap  = g_act_t + b;
    const float* rp_ = g_rew_t + b;
    ull (*stw)[8][18] = &st[wid][0];   // this warp's [parity][e][pair]

    if (is_rew) {
        // ---------------- reward module ----------------
        ull bw[8], w2s[4];
        #pragma unroll
        for (int r = 0; r < 8; r++) {
            const int row = 8 * ll + r;
            bw[r] = pack2(b_r1[row] * TANH_SC, w_r1[row * 33] * TANH_SC);
        }
        #pragma unroll
        for (int u = 0; u < 4; u++)
            w2s[u] = pack2(w_r2[8 * ll + 2 * u], w_r2[8 * ll + 2 * u + 1]);
        const float br2 = b_r2[0];
        float q = 0.0f;
        float* op = out + ((size_t)b * NSTEP) * 4 + ll;

        int   a_cur = ap[0];
        float r_cur = rp_[0];
        for (int t = 0; t < NSTEP; t++) {
            const int   a_nxt = ap[(t + 1) * B_SZ];
            const float r_nxt = rp_[(t + 1) * B_SZ];

            const ull rv = pack2(1.0f, r_cur);
            ull acc[8];
            #pragma unroll
            for (int r = 0; r < 8; r++) acc[r] = mul2(bw[r], rv);  // {b', wc0'*r}

            const ull* sb = &stw[t & 1][e][0];
            #pragma unroll
            for (int pp = 0; pp < 8; pp++) {
                const ulonglong2 sv = *(const ulonglong2*)&sb[2 * pp];
                #pragma unroll
                for (int r = 0; r < 8; r++) {
                    const ulonglong2 w = *(const ulonglong2*)&w1s[ll][r * 16 + 2 * pp];
                    ffma2(acc[r], w.x, sv.x);
                    ffma2(acc[r], w.y, sv.y);
                }
            }
            float sn[8];
            #pragma unroll
            for (int r = 0; r < 8; r++) {
                const float2 u = unpack2(acc[r]);
                sn[r] = tanh_pre(u.x + u.y);
            }
            ull sp[4];
            #pragma unroll
            for (int u = 0; u < 4; u++) sp[u] = pack2(sn[2 * u], sn[2 * u + 1]);

            ull* wb = &stw[(t + 1) & 1][e][0];
            *(ulonglong2*)&wb[4 * ll]     = make_ulonglong2(sp[0], sp[1]);
            *(ulonglong2*)&wb[4 * ll + 2] = make_ulonglong2(sp[2], sp[3]);
            __syncwarp();

            // q_new = w_r2 . s + b_r2 : own-8-dims partial + 4-lane reduce
            ull qa = 0ull;
            #pragma unroll
            for (int u = 0; u < 4; u++) ffma2(qa, w2s[u], sp[u]);
            const float2 qf = unpack2(qa);
            float qs = qf.x + qf.y;
            qs += __shfl_xor_sync(0xFFFFFFFFu, qs, 1);
            qs += __shfl_xor_sync(0xFFFFFFFFu, qs, 2);
            const float q_new = qs + br2;

            q = (a_cur == ll) ? q_new : q * 0.95f;
            op[(size_t)t * 4] = q;

            a_cur = a_nxt; r_cur = r_nxt;
        }
    } else {
        // ---------------- action-history module ----------------
        ull w2a[4][4];
        #pragma unroll
        for (int k = 0; k < 4; k++)
            #pragma unroll
            for (int u = 0; u < 4; u++)
                w2a[k][u] = pack2(w_a2[k * 32 + 8 * ll + 2 * u],
                                  w_a2[k * 32 + 8 * ll + 2 * u + 1]);
        const float ba = b_a2[ll];
        float* cp = g_c + ((size_t)b * NSTEP) * 4 + ll;

        int a_cur = ap[0];
        for (int t = 0; t < NSTEP; t++) {
            const int a_nxt = ap[(t + 1) * B_SZ];

            ull acc[8];
            #pragma unroll
            for (int r = 0; r < 8; r++) acc[r] = 0ull;

            const ull* sb = &stw[t & 1][e][0];
            #pragma unroll
            for (int pp = 0; pp < 8; pp++) {
                const ulonglong2 sv = *(const ulonglong2*)&sb[2 * pp];
                #pragma unroll
                for (int r = 0; r < 8; r++) {
                    const ulonglong2 w = *(const ulonglong2*)&w1s[ll][r * 16 + 2 * pp];
                    ffma2(acc[r], w.x, sv.x);
                    ffma2(acc[r], w.y, sv.y);
                }
            }
            const ulonglong2 cbA = *(const ulonglong2*)&colba[a_cur][ll][0];
            const ulonglong2 cbB = *(const ulonglong2*)&colba[a_cur][ll][2];
            const float2 c0f = unpack2(cbA.x), c1f = unpack2(cbA.y);
            const float2 c2f = unpack2(cbB.x), c3f = unpack2(cbB.y);
            const float cbv[8] = {c0f.x, c0f.y, c1f.x, c1f.y,
                                  c2f.x, c2f.y, c3f.x, c3f.y};

            float sn[8];
            #pragma unroll
            for (int r = 0; r < 8; r++) {
                const float2 u = unpack2(acc[r]);
                sn[r] = tanh_pre(u.x + u.y + cbv[r]);
            }
            ull sp[4];
            #pragma unroll
            for (int u = 0; u < 4; u++) sp[u] = pack2(sn[2 * u], sn[2 * u + 1]);

            ull* wb = &stw[(t + 1) & 1][e][0];
            *(ulonglong2*)&wb[4 * ll]     = make_ulonglong2(sp[0], sp[1]);
            *(ulonglong2*)&wb[4 * ll + 2] = make_ulonglong2(sp[2], sp[3]);
            __syncwarp();

            // c_k partials over own 8 dims, packed 4-lane reduce
            ull ca0 = 0ull, ca1 = 0ull, ca2 = 0ull, ca3 = 0ull;
            #pragma unroll
            for (int u = 0; u < 4; u++) {
                ffma2(ca0, w2a[0][u], sp[u]);
                ffma2(ca1, w2a[1][u], sp[u]);
                ffma2(ca2, w2a[2][u], sp[u]);
                ffma2(ca3, w2a[3][u], sp[u]);
            }
            const float2 f0 = unpack2(ca0), f1 = unpack2(ca1);
            const float2 f2 = unpack2(ca2), f3 = unpack2(ca3);
            ull v01 = pack2(f0.x + f0.y, f1.x + f1.y);
            ull v23 = pack2(f2.x + f2.y, f3.x + f3.y);
            v01 = add2(v01, shflx64(v01, 1));
            v23 = add2(v23, shflx64(v23, 1));
            v01 = add2(v01, shflx64(v01, 2));
            v23 = add2(v23, shflx64(v23, 2));
            const ull    vsel = (ll & 2) ? v23 : v01;
            const float2 vv   = unpack2(vsel);
            cp[(size_t)t * 4] = ((ll & 1) ? vv.y : vv.x) + ba;

            a_cur = a_nxt;
        }
    }
}

// ---------------- out += c ----------------
__global__ void __launch_bounds__(256)
add_kernel(float* __restrict__ out) {
    const size_t n4 = (size_t)B_SZ * NSTEP;
    float4* o = (float4*)out;
    const float4* c = (const float4*)g_c;
    for (size_t i = (size_t)blockIdx.x * 256 + threadIdx.x; i < n4;
         i += (size_t)gridDim.x * 256) {
        float4 a = o[i], b = c[i];
        a.x += b.x; a.y += b.y; a.z += b.z; a.w += b.w;
        o[i] = a;
    }
}

extern "C" void kernel_launch(void* const* d_in, const int* in_sizes, int n_in,
                              void* d_out, int out_size) {
    (void)in_sizes; (void)n_in; (void)out_size;
    transpose_kernel<<<dim3(T_LEN / 32, B_SZ / 32, 2), dim3(32, 8)>>>(
        (const int*)d_in[0], (const float*)d_in[1]);
    memann_mod<<<1024, 64>>>(
        (const float*)d_in[2], (const float*)d_in[3],
        (const float*)d_in[4], (const float*)d_in[5],
        (const float*)d_in[6], (const float*)d_in[7],
        (const float*)d_in[8], (const float*)d_in[9],
        (float*)d_out);
    add_kernel<<<2048, 256>>>((float*)d_out);
}